// round 7
// baseline (speedup 1.0000x reference)
#include <cuda_runtime.h>
#include <cuda_bf16.h>

#define NN 50000
#define NE 800000
#define D  64
#define WPAD 68
#define NODES_PER_BLK 16
#define SCAN_THREADS 1024
#define SCAN_ITEMS 49            // ceil(50000 / 1024)

// Scratch (allocations forbidden; __device__ globals are the sanctioned path)
__device__ __align__(16) float g_msgs[NN * D];  // x @ Wm^T + bm
__device__ int g_counts[NN];                    // in-degree (counting sort pass 1)
__device__ int g_offsets[NN + 1];               // CSR row offsets (exclusive scan)
__device__ int g_cursor[NN];                    // fill cursors for position scatter
__device__ int g_srcs[NE];                      // destination-grouped source ids

// ---------------------------------------------------------------------------
// Kernel 1: zero the degree counters (graph replays re-run the whole pipeline)
// ---------------------------------------------------------------------------
__global__ void zero_counts_kernel() {
    int gid = blockIdx.x * blockDim.x + threadIdx.x;
    if (gid < NN) g_counts[gid] = 0;
}

// ---------------------------------------------------------------------------
// Kernel 2: fused dual GEMM (unchanged from the passing R6 kernel).
//   g_msgs = x @ Wm^T + bm   (feeds the gather)
//   out    = x @ Ws^T + bs   (self projection, written straight to d_out)
// ---------------------------------------------------------------------------
__global__ __launch_bounds__(256) void dual_gemm_kernel(
    const float* __restrict__ x,
    const float* __restrict__ Wm, const float* __restrict__ bm,
    const float* __restrict__ Ws, const float* __restrict__ bs,
    float* __restrict__ out)
{
    __shared__ float wm_sh[D * WPAD];
    __shared__ float ws_sh[D * WPAD];
    __shared__ float x_sh[NODES_PER_BLK * WPAD];

    const int t = threadIdx.x;
    const int nbase = blockIdx.x * NODES_PER_BLK;

    for (int i = t; i < D * D; i += 256) {
        int d = i >> 6;
        int k = i & 63;
        wm_sh[k * WPAD + d] = Wm[i];
        ws_sh[k * WPAD + d] = Ws[i];
    }
    {
        int node = t >> 4;
        int c4   = (t & 15) * 4;
        float4 v = *reinterpret_cast<const float4*>(&x[(nbase + node) * D + c4]);
        *reinterpret_cast<float4*>(&x_sh[node * WPAD + c4]) = v;
    }
    __syncthreads();

    const int node = t >> 4;
    const int dq   = (t & 15) * 4;

    float4 am = make_float4(0.f, 0.f, 0.f, 0.f);
    float4 av = make_float4(0.f, 0.f, 0.f, 0.f);

#pragma unroll
    for (int k = 0; k < D; ++k) {
        float xv = x_sh[node * WPAD + k];
        float4 w1 = *reinterpret_cast<const float4*>(&wm_sh[k * WPAD + dq]);
        am.x = fmaf(xv, w1.x, am.x);
        am.y = fmaf(xv, w1.y, am.y);
        am.z = fmaf(xv, w1.z, am.z);
        am.w = fmaf(xv, w1.w, am.w);
        float4 w2 = *reinterpret_cast<const float4*>(&ws_sh[k * WPAD + dq]);
        av.x = fmaf(xv, w2.x, av.x);
        av.y = fmaf(xv, w2.y, av.y);
        av.z = fmaf(xv, w2.z, av.z);
        av.w = fmaf(xv, w2.w, av.w);
    }

    float4 bmv = *reinterpret_cast<const float4*>(&bm[dq]);
    float4 bsv = *reinterpret_cast<const float4*>(&bs[dq]);
    am.x += bmv.x; am.y += bmv.y; am.z += bmv.z; am.w += bmv.w;
    av.x += bsv.x; av.y += bsv.y; av.z += bsv.z; av.w += bsv.w;

    const int o = (nbase + node) * D + dq;
    *reinterpret_cast<float4*>(&g_msgs[o]) = am;
    *reinterpret_cast<float4*>(&out[o])    = av;
}

// ---------------------------------------------------------------------------
// Kernel 3: degree histogram. 800k int atomics over 50k counters (L2-fast).
// ---------------------------------------------------------------------------
__global__ __launch_bounds__(256) void count_kernel(const int* __restrict__ ei) {
    int e = blockIdx.x * 256 + threadIdx.x;
    if (e < NE) {
        int c = __ldg(&ei[NE + e]);
        c = min(max(c, 0), NN - 1);
        atomicAdd(&g_counts[c], 1);
    }
}

// ---------------------------------------------------------------------------
// Kernel 4: exclusive scan of degrees -> CSR offsets + fill cursors.
// Single block, 1024 threads, 49 items/thread. Two global passes
// (sum, then emit) + one Kogge-Stone smem scan of the 1024 partials.
// ---------------------------------------------------------------------------
__global__ __launch_bounds__(SCAN_THREADS) void scan_kernel() {
    __shared__ int s[SCAN_THREADS];
    const int t = threadIdx.x;
    const int base = t * SCAN_ITEMS;

    int sum = 0;
#pragma unroll
    for (int i = 0; i < SCAN_ITEMS; ++i) {
        int idx = base + i;
        if (idx < NN) sum += g_counts[idx];
    }
    s[t] = sum;
    __syncthreads();

#pragma unroll
    for (int off = 1; off < SCAN_THREADS; off <<= 1) {
        int v = (t >= off) ? s[t - off] : 0;
        __syncthreads();
        s[t] += v;
        __syncthreads();
    }

    int run = (t > 0) ? s[t - 1] : 0;  // exclusive prefix of this chunk
#pragma unroll
    for (int i = 0; i < SCAN_ITEMS; ++i) {
        int idx = base + i;
        if (idx < NN) {
            int c = g_counts[idx];
            g_offsets[idx] = run;
            g_cursor[idx]  = run;
            run += c;
        }
    }
    if (t == SCAN_THREADS - 1) g_offsets[NN] = run;  // == NE
}

// ---------------------------------------------------------------------------
// Kernel 5: position scatter. Each edge claims a slot in its destination's
// CSR segment and records its SOURCE id there. 800k returning int atomics.
// ---------------------------------------------------------------------------
__global__ __launch_bounds__(256) void pos_kernel(const int* __restrict__ ei) {
    int e = blockIdx.x * 256 + threadIdx.x;
    if (e < NE) {
        int r = __ldg(&ei[e]);
        int c = __ldg(&ei[NE + e]);
        r = min(max(r, 0), NN - 1);
        c = min(max(c, 0), NN - 1);
        int p = atomicAdd(&g_cursor[c], 1);
        g_srcs[p] = r;
    }
}

// ---------------------------------------------------------------------------
// Kernel 6: warp-per-node gather + mean + self-add. ZERO atomics.
// Lane l accumulates dims l and l+32: per edge two coalesced 128B loads of
// g_msgs[src] (L2-resident). 50k warps chip-wide hide the L2 latency.
// Manual 2x unroll for memory-level parallelism across edges.
// ---------------------------------------------------------------------------
__global__ __launch_bounds__(256) void aggregate_kernel(float* __restrict__ out) {
    const int node = blockIdx.x * 8 + (threadIdx.x >> 5);
    if (node >= NN) return;
    const int lane = threadIdx.x & 31;

    const int start = __ldg(&g_offsets[node]);
    const int end   = __ldg(&g_offsets[node + 1]);

    float a0 = 0.f, a1 = 0.f;
    int j = start;
    for (; j + 2 <= end; j += 2) {
        int s0 = __ldg(&g_srcs[j]);
        int s1 = __ldg(&g_srcs[j + 1]);
        float v00 = __ldg(&g_msgs[s0 * D + lane]);
        float v01 = __ldg(&g_msgs[s0 * D + 32 + lane]);
        float v10 = __ldg(&g_msgs[s1 * D + lane]);
        float v11 = __ldg(&g_msgs[s1 * D + 32 + lane]);
        a0 += v00 + v10;
        a1 += v01 + v11;
    }
    if (j < end) {
        int s0 = __ldg(&g_srcs[j]);
        a0 += __ldg(&g_msgs[s0 * D + lane]);
        a1 += __ldg(&g_msgs[s0 * D + 32 + lane]);
    }

    const float inv = 1.0f / fmaxf((float)(end - start), 1.0f);
    const int o = node * D + lane;
    out[o]      = fmaf(a0, inv, out[o]);
    out[o + 32] = fmaf(a1, inv, out[o + 32]);
}

// ---------------------------------------------------------------------------
extern "C" void kernel_launch(void* const* d_in, const int* in_sizes, int n_in,
                              void* d_out, int out_size)
{
    const float* x   = (const float*)d_in[0];
    const int*   ei  = (const int*)d_in[1];    // int32 (JAX x64-disabled)
    const float* Wm  = (const float*)d_in[2];
    const float* bm  = (const float*)d_in[3];
    const float* Ws  = (const float*)d_in[4];
    const float* bs  = (const float*)d_in[5];
    float*       out = (float*)d_out;

    (void)in_sizes; (void)n_in; (void)out_size;

    // 1) zero degree counters
    zero_counts_kernel<<<(NN + 255) / 256, 256>>>();

    // 2) dual GEMM (independent of CSR build; writes g_msgs and self-proj out)
    dual_gemm_kernel<<<NN / NODES_PER_BLK, 256>>>(x, Wm, bm, Ws, bs, out);

    // 3) degree histogram
    count_kernel<<<(NE + 255) / 256, 256>>>(ei);

    // 4) exclusive scan -> offsets + cursors (single block)
    scan_kernel<<<1, SCAN_THREADS>>>();

    // 5) position scatter -> destination-grouped source list
    pos_kernel<<<(NE + 255) / 256, 256>>>(ei);

    // 6) gather + mean + self-add (atomic-free), fuses old finalize
    aggregate_kernel<<<(NN + 7) / 8, 256>>>(out);
}

// round 8
// speedup vs baseline: 1.6157x; 1.6157x over previous
#include <cuda_runtime.h>
#include <cuda_bf16.h>

#define NN 50000
#define NE 800000
#define D  64
#define WPAD 68
#define NODES_PER_BLK 16
#define SCAN_BLOCKS 196          // 196*256 = 50176 >= NN

// Scratch (allocations forbidden; __device__ globals are the sanctioned path)
__device__ __align__(16) float g_msgs[NN * D];  // x @ Wm^T + bm
__device__ int g_counts[NN];                    // in-degree (counting sort pass 1)
__device__ int g_offsets[NN + 1];               // CSR row offsets (exclusive scan)
__device__ int g_cursor[NN];                    // fill cursors for position scatter
__device__ int g_srcs[NE];                      // destination-grouped source ids
__device__ int g_bsums[SCAN_BLOCKS];            // per-block sums for grid scan

// ---------------------------------------------------------------------------
// Kernel 1: zero the degree counters (graph replays re-run the whole pipeline)
// ---------------------------------------------------------------------------
__global__ void zero_counts_kernel() {
    int gid = blockIdx.x * blockDim.x + threadIdx.x;
    if (gid < NN) g_counts[gid] = 0;
}

// ---------------------------------------------------------------------------
// Kernel 2: fused dual GEMM.
//   g_msgs = x @ Wm^T + bm   (feeds the gather)
//   out    = x @ Ws^T + bs   (self projection, written straight to d_out)
// ---------------------------------------------------------------------------
__global__ __launch_bounds__(256) void dual_gemm_kernel(
    const float* __restrict__ x,
    const float* __restrict__ Wm, const float* __restrict__ bm,
    const float* __restrict__ Ws, const float* __restrict__ bs,
    float* __restrict__ out)
{
    __shared__ float wm_sh[D * WPAD];
    __shared__ float ws_sh[D * WPAD];
    __shared__ float x_sh[NODES_PER_BLK * WPAD];

    const int t = threadIdx.x;
    const int nbase = blockIdx.x * NODES_PER_BLK;

    for (int i = t; i < D * D; i += 256) {
        int d = i >> 6;
        int k = i & 63;
        wm_sh[k * WPAD + d] = Wm[i];
        ws_sh[k * WPAD + d] = Ws[i];
    }
    {
        int node = t >> 4;
        int c4   = (t & 15) * 4;
        float4 v = *reinterpret_cast<const float4*>(&x[(nbase + node) * D + c4]);
        *reinterpret_cast<float4*>(&x_sh[node * WPAD + c4]) = v;
    }
    __syncthreads();

    const int node = t >> 4;
    const int dq   = (t & 15) * 4;

    float4 am = make_float4(0.f, 0.f, 0.f, 0.f);
    float4 av = make_float4(0.f, 0.f, 0.f, 0.f);

#pragma unroll
    for (int k = 0; k < D; ++k) {
        float xv = x_sh[node * WPAD + k];
        float4 w1 = *reinterpret_cast<const float4*>(&wm_sh[k * WPAD + dq]);
        am.x = fmaf(xv, w1.x, am.x);
        am.y = fmaf(xv, w1.y, am.y);
        am.z = fmaf(xv, w1.z, am.z);
        am.w = fmaf(xv, w1.w, am.w);
        float4 w2 = *reinterpret_cast<const float4*>(&ws_sh[k * WPAD + dq]);
        av.x = fmaf(xv, w2.x, av.x);
        av.y = fmaf(xv, w2.y, av.y);
        av.z = fmaf(xv, w2.z, av.z);
        av.w = fmaf(xv, w2.w, av.w);
    }

    float4 bmv = *reinterpret_cast<const float4*>(&bm[dq]);
    float4 bsv = *reinterpret_cast<const float4*>(&bs[dq]);
    am.x += bmv.x; am.y += bmv.y; am.z += bmv.z; am.w += bmv.w;
    av.x += bsv.x; av.y += bsv.y; av.z += bsv.z; av.w += bsv.w;

    const int o = (nbase + node) * D + dq;
    *reinterpret_cast<float4*>(&g_msgs[o]) = am;
    *reinterpret_cast<float4*>(&out[o])    = av;
}

// ---------------------------------------------------------------------------
// Kernel 3: degree histogram. 800k int atomics over 50k counters (L2-fast).
// ---------------------------------------------------------------------------
__global__ __launch_bounds__(256) void count_kernel(const int* __restrict__ ei) {
    int e = blockIdx.x * 256 + threadIdx.x;
    if (e < NE) {
        int c = __ldg(&ei[NE + e]);
        c = min(max(c, 0), NN - 1);
        atomicAdd(&g_counts[c], 1);
    }
}

// ---------------------------------------------------------------------------
// Grid scan (3 kernels), replacing the 83us single-block scan.
// scan1: per-block exclusive scan of counts -> local prefix + block sum.
// ---------------------------------------------------------------------------
__device__ __forceinline__ int warp_incl_scan(int v, int lane) {
#pragma unroll
    for (int off = 1; off < 32; off <<= 1) {
        int n = __shfl_up_sync(0xFFFFFFFFu, v, off);
        if (lane >= off) v += n;
    }
    return v;
}

__global__ __launch_bounds__(256) void scan1_kernel() {
    __shared__ int wsum[8];
    const int t = threadIdx.x;
    const int lane = t & 31;
    const int w = t >> 5;
    const int idx = blockIdx.x * 256 + t;

    int v = (idx < NN) ? g_counts[idx] : 0;
    int inc = warp_incl_scan(v, lane);
    if (lane == 31) wsum[w] = inc;
    __syncthreads();

    if (w == 0) {
        int s = (lane < 8) ? wsum[lane] : 0;
        int si = warp_incl_scan(s, lane);
        if (lane < 8) wsum[lane] = si - s;   // exclusive warp offsets
        if (lane == 7 && blockIdx.x < SCAN_BLOCKS) g_bsums[blockIdx.x] = si;
    }
    __syncthreads();

    if (idx < NN) g_offsets[idx] = inc - v + wsum[w];   // block-local exclusive
}

// scan2: one warp exclusive-scans the 196 block sums (serial chunks of 32).
__global__ void scan2_kernel() {
    const int lane = threadIdx.x;   // 32 threads
    int run = 0;
    for (int base = 0; base < SCAN_BLOCKS; base += 32) {
        int i = base + lane;
        int v = (i < SCAN_BLOCKS) ? g_bsums[i] : 0;
        int inc = warp_incl_scan(v, lane);
        if (i < SCAN_BLOCKS) g_bsums[i] = run + inc - v;
        run += __shfl_sync(0xFFFFFFFFu, inc, 31);
    }
    if (lane == 0) g_offsets[NN] = NE;   // every (clamped) edge is counted
}

// scan3: add block offsets, materialize offsets + fill cursors.
__global__ __launch_bounds__(256) void scan3_kernel() {
    const int idx = blockIdx.x * 256 + threadIdx.x;
    if (idx < NN) {
        int o = g_offsets[idx] + g_bsums[blockIdx.x];
        g_offsets[idx] = o;
        g_cursor[idx]  = o;
    }
}

// ---------------------------------------------------------------------------
// Kernel 5: position scatter. Each edge claims a slot in its destination's
// CSR segment and records its SOURCE id there. 800k returning int atomics.
// ---------------------------------------------------------------------------
__global__ __launch_bounds__(256) void pos_kernel(const int* __restrict__ ei) {
    int e = blockIdx.x * 256 + threadIdx.x;
    if (e < NE) {
        int r = __ldg(&ei[e]);
        int c = __ldg(&ei[NE + e]);
        r = min(max(r, 0), NN - 1);
        c = min(max(c, 0), NN - 1);
        int p = atomicAdd(&g_cursor[c], 1);
        g_srcs[p] = r;
    }
}

// ---------------------------------------------------------------------------
// Kernel 6: warp-per-node gather + mean + self-add. ZERO atomics.
// Lane l accumulates dims l and l+32. 4x edge unroll for MLP (8 independent
// 128B loads in flight per warp iteration); avg degree = 16.
// ---------------------------------------------------------------------------
__global__ __launch_bounds__(256) void aggregate_kernel(float* __restrict__ out) {
    const int node = blockIdx.x * 8 + (threadIdx.x >> 5);
    if (node >= NN) return;
    const int lane = threadIdx.x & 31;

    const int start = __ldg(&g_offsets[node]);
    const int end   = __ldg(&g_offsets[node + 1]);

    float a0 = 0.f, a1 = 0.f;
    int j = start;
    for (; j + 4 <= end; j += 4) {
        int s0 = __ldg(&g_srcs[j]);
        int s1 = __ldg(&g_srcs[j + 1]);
        int s2 = __ldg(&g_srcs[j + 2]);
        int s3 = __ldg(&g_srcs[j + 3]);
        float v00 = __ldg(&g_msgs[s0 * D + lane]);
        float v01 = __ldg(&g_msgs[s0 * D + 32 + lane]);
        float v10 = __ldg(&g_msgs[s1 * D + lane]);
        float v11 = __ldg(&g_msgs[s1 * D + 32 + lane]);
        float v20 = __ldg(&g_msgs[s2 * D + lane]);
        float v21 = __ldg(&g_msgs[s2 * D + 32 + lane]);
        float v30 = __ldg(&g_msgs[s3 * D + lane]);
        float v31 = __ldg(&g_msgs[s3 * D + 32 + lane]);
        a0 += (v00 + v10) + (v20 + v30);
        a1 += (v01 + v11) + (v21 + v31);
    }
    for (; j < end; ++j) {
        int s0 = __ldg(&g_srcs[j]);
        a0 += __ldg(&g_msgs[s0 * D + lane]);
        a1 += __ldg(&g_msgs[s0 * D + 32 + lane]);
    }

    const float inv = 1.0f / fmaxf((float)(end - start), 1.0f);
    const int o = node * D + lane;
    out[o]      = fmaf(a0, inv, out[o]);
    out[o + 32] = fmaf(a1, inv, out[o + 32]);
}

// ---------------------------------------------------------------------------
extern "C" void kernel_launch(void* const* d_in, const int* in_sizes, int n_in,
                              void* d_out, int out_size)
{
    const float* x   = (const float*)d_in[0];
    const int*   ei  = (const int*)d_in[1];    // int32 (JAX x64-disabled)
    const float* Wm  = (const float*)d_in[2];
    const float* bm  = (const float*)d_in[3];
    const float* Ws  = (const float*)d_in[4];
    const float* bs  = (const float*)d_in[5];
    float*       out = (float*)d_out;

    (void)in_sizes; (void)n_in; (void)out_size;

    // 1) zero degree counters
    zero_counts_kernel<<<(NN + 255) / 256, 256>>>();

    // 2) dual GEMM (independent of CSR build)
    dual_gemm_kernel<<<NN / NODES_PER_BLK, 256>>>(x, Wm, bm, Ws, bs, out);

    // 3) degree histogram
    count_kernel<<<(NE + 255) / 256, 256>>>(ei);

    // 4) grid scan -> offsets + cursors
    scan1_kernel<<<SCAN_BLOCKS, 256>>>();
    scan2_kernel<<<1, 32>>>();
    scan3_kernel<<<SCAN_BLOCKS, 256>>>();

    // 5) position scatter -> destination-grouped source list
    pos_kernel<<<(NE + 255) / 256, 256>>>(ei);

    // 6) gather + mean + self-add (atomic-free)
    aggregate_kernel<<<(NN + 7) / 8, 256>>>(out);
}

// round 11
// speedup vs baseline: 2.5683x; 1.5895x over previous
#include <cuda_runtime.h>
#include <cuda_bf16.h>

#define NN 50000
#define NE 800000
#define D  64
#define WPAD 68
#define NBLK 64                  // nodes per GEMM block (4 per thread)
#define GEMM_BLOCKS ((NN + NBLK - 1) / NBLK)   // 782
#define SCAN_BLOCKS 196          // 196*256 = 50176 >= NN

// Scratch (allocations forbidden; __device__ globals are the sanctioned path)
__device__ __align__(16) float g_msgs[NN * D];  // x @ Wm^T + bm
__device__ int g_counts[NN];                    // in-degree (counting sort pass 1)
__device__ int g_offsets[NN + 1];               // CSR row offsets (exclusive scan)
__device__ int g_cursor[NN];                    // fill cursors for position scatter
__device__ int g_srcs[NE];                      // destination-grouped source ids
__device__ int g_bsums[SCAN_BLOCKS];            // per-block sums for grid scan

// ---------------------------------------------------------------------------
// Kernel 1: zero the degree counters (graph replays re-run the whole pipeline)
// ---------------------------------------------------------------------------
__global__ void zero_counts_kernel() {
    int gid = blockIdx.x * blockDim.x + threadIdx.x;
    if (gid < NN) g_counts[gid] = 0;
}

// ---------------------------------------------------------------------------
// Kernel 2: fused dual GEMM (4-node register blocking) + degree histogram.
//   g_msgs = x @ Wm^T + bm   (feeds the gather)
//   out    = x @ Ws^T + bs   (self projection, straight to d_out)
// Thread = (node-group g of 4 nodes, dim-quad dq). Per k-step: 2 LDS.128 (W)
// + 4 broadcast LDS (x) feed 32 FMA -> 1.5 smem-B/FMA (was 4.5): FMA-bound.
// The degree histogram rides along as a grid-stride loop (REDG, no return),
// hidden under the FMA mainloop; saves a separate launch.
// ---------------------------------------------------------------------------
__global__ __launch_bounds__(256) void dual_gemm_kernel(
    const float* __restrict__ x,
    const float* __restrict__ Wm, const float* __restrict__ bm,
    const float* __restrict__ Ws, const float* __restrict__ bs,
    const int*   __restrict__ ei,
    float* __restrict__ out)
{
    __shared__ float wm_sh[D * WPAD];
    __shared__ float ws_sh[D * WPAD];
    __shared__ float x_sh[NBLK * WPAD];

    const int t = threadIdx.x;
    const int nbase = blockIdx.x * NBLK;

    // Fused degree histogram: 782*256 = 200192 threads, 4 edges each.
    for (int e = blockIdx.x * 256 + t; e < NE; e += GEMM_BLOCKS * 256) {
        int c = __ldg(&ei[NE + e]);
        c = min(max(c, 0), NN - 1);
        atomicAdd(&g_counts[c], 1);
    }

    // Load both W matrices transposed: Wsh[k][d] = W[d][k]
    for (int i = t; i < D * D; i += 256) {
        int d = i >> 6;
        int k = i & 63;
        wm_sh[k * WPAD + d] = Wm[i];
        ws_sh[k * WPAD + d] = Ws[i];
    }
    // Load x tile (64 nodes x 64) via float4; clamp OOB rows (stores predicated)
    for (int v = t; v < NBLK * 16; v += 256) {
        int row = v >> 4;
        int c4  = (v & 15) * 4;
        int gnode = min(nbase + row, NN - 1);
        float4 xv = *reinterpret_cast<const float4*>(&x[gnode * D + c4]);
        *reinterpret_cast<float4*>(&x_sh[row * WPAD + c4]) = xv;
    }
    __syncthreads();

    const int g  = t >> 4;          // node group 0..15 (4 nodes each)
    const int dq = (t & 15) * 4;    // output dim quad

    float4 am[4], av[4];
#pragma unroll
    for (int j = 0; j < 4; ++j) {
        am[j] = make_float4(0.f, 0.f, 0.f, 0.f);
        av[j] = make_float4(0.f, 0.f, 0.f, 0.f);
    }

#pragma unroll
    for (int k = 0; k < D; ++k) {
        float4 w1 = *reinterpret_cast<const float4*>(&wm_sh[k * WPAD + dq]);
        float4 w2 = *reinterpret_cast<const float4*>(&ws_sh[k * WPAD + dq]);
#pragma unroll
        for (int j = 0; j < 4; ++j) {
            float xv = x_sh[(g * 4 + j) * WPAD + k];
            am[j].x = fmaf(xv, w1.x, am[j].x);
            am[j].y = fmaf(xv, w1.y, am[j].y);
            am[j].z = fmaf(xv, w1.z, am[j].z);
            am[j].w = fmaf(xv, w1.w, am[j].w);
            av[j].x = fmaf(xv, w2.x, av[j].x);
            av[j].y = fmaf(xv, w2.y, av[j].y);
            av[j].z = fmaf(xv, w2.z, av[j].z);
            av[j].w = fmaf(xv, w2.w, av[j].w);
        }
    }

    float4 bmv = *reinterpret_cast<const float4*>(&bm[dq]);
    float4 bsv = *reinterpret_cast<const float4*>(&bs[dq]);
#pragma unroll
    for (int j = 0; j < 4; ++j) {
        int node = nbase + g * 4 + j;
        if (node < NN) {
            float4 a = am[j], v = av[j];
            a.x += bmv.x; a.y += bmv.y; a.z += bmv.z; a.w += bmv.w;
            v.x += bsv.x; v.y += bsv.y; v.z += bsv.z; v.w += bsv.w;
            const int o = node * D + dq;
            *reinterpret_cast<float4*>(&g_msgs[o]) = a;
            *reinterpret_cast<float4*>(&out[o])    = v;
        }
    }
}

// ---------------------------------------------------------------------------
// Grid scan (3 kernels).
// ---------------------------------------------------------------------------
__device__ __forceinline__ int warp_incl_scan(int v, int lane) {
#pragma unroll
    for (int off = 1; off < 32; off <<= 1) {
        int n = __shfl_up_sync(0xFFFFFFFFu, v, off);
        if (lane >= off) v += n;
    }
    return v;
}

__global__ __launch_bounds__(256) void scan1_kernel() {
    __shared__ int wsum[8];
    const int t = threadIdx.x;
    const int lane = t & 31;
    const int w = t >> 5;
    const int idx = blockIdx.x * 256 + t;

    int v = (idx < NN) ? g_counts[idx] : 0;
    int inc = warp_incl_scan(v, lane);
    if (lane == 31) wsum[w] = inc;
    __syncthreads();

    if (w == 0) {
        int s = (lane < 8) ? wsum[lane] : 0;
        int si = warp_incl_scan(s, lane);
        if (lane < 8) wsum[lane] = si - s;   // exclusive warp offsets
        if (lane == 7) g_bsums[blockIdx.x] = si;
    }
    __syncthreads();

    if (idx < NN) g_offsets[idx] = inc - v + wsum[w];   // block-local exclusive
}

__global__ void scan2_kernel() {
    const int lane = threadIdx.x;   // 32 threads
    int run = 0;
    for (int base = 0; base < SCAN_BLOCKS; base += 32) {
        int i = base + lane;
        int v = (i < SCAN_BLOCKS) ? g_bsums[i] : 0;
        int inc = warp_incl_scan(v, lane);
        if (i < SCAN_BLOCKS) g_bsums[i] = run + inc - v;
        run += __shfl_sync(0xFFFFFFFFu, inc, 31);
    }
    if (lane == 0) g_offsets[NN] = NE;   // every (clamped) edge is counted
}

__global__ __launch_bounds__(256) void scan3_kernel() {
    const int idx = blockIdx.x * 256 + threadIdx.x;
    if (idx < NN) {
        int o = g_offsets[idx] + g_bsums[blockIdx.x];
        g_offsets[idx] = o;
        g_cursor[idx]  = o;
    }
}

// ---------------------------------------------------------------------------
// Position scatter: each edge claims a slot in its destination's CSR segment
// and records its SOURCE id there. 800k returning int atomics.
// ---------------------------------------------------------------------------
__global__ __launch_bounds__(256) void pos_kernel(const int* __restrict__ ei) {
    int e = blockIdx.x * 256 + threadIdx.x;
    if (e < NE) {
        int r = __ldg(&ei[e]);
        int c = __ldg(&ei[NE + e]);
        r = min(max(r, 0), NN - 1);
        c = min(max(c, 0), NN - 1);
        int p = atomicAdd(&g_cursor[c], 1);
        g_srcs[p] = r;
    }
}

// ---------------------------------------------------------------------------
// Warp-per-node gather + mean + self-add. ZERO atomics.
// Lane l owns dims {2l, 2l+1} via float2 (LDG.64): one load per edge per lane
// (was two LDG.32) -> half the LSU/L1tex wavefront pressure. 4x edge unroll
// keeps 4 independent 64-bit loads in flight (avg degree 16).
// ---------------------------------------------------------------------------
__global__ __launch_bounds__(256) void aggregate_kernel(float* __restrict__ out) {
    const int node = blockIdx.x * 8 + (threadIdx.x >> 5);
    if (node >= NN) return;
    const int lane = threadIdx.x & 31;

    const int start = __ldg(&g_offsets[node]);
    const int end   = __ldg(&g_offsets[node + 1]);

    const float2* __restrict__ msgs2 = reinterpret_cast<const float2*>(g_msgs);

    float ax = 0.f, ay = 0.f;
    int j = start;
    for (; j + 4 <= end; j += 4) {
        int s0 = __ldg(&g_srcs[j]);
        int s1 = __ldg(&g_srcs[j + 1]);
        int s2 = __ldg(&g_srcs[j + 2]);
        int s3 = __ldg(&g_srcs[j + 3]);
        float2 v0 = __ldg(&msgs2[s0 * 32 + lane]);
        float2 v1 = __ldg(&msgs2[s1 * 32 + lane]);
        float2 v2 = __ldg(&msgs2[s2 * 32 + lane]);
        float2 v3 = __ldg(&msgs2[s3 * 32 + lane]);
        ax += (v0.x + v1.x) + (v2.x + v3.x);
        ay += (v0.y + v1.y) + (v2.y + v3.y);
    }
    for (; j < end; ++j) {
        int s0 = __ldg(&g_srcs[j]);
        float2 v0 = __ldg(&msgs2[s0 * 32 + lane]);
        ax += v0.x;
        ay += v0.y;
    }

    const float inv = 1.0f / fmaxf((float)(end - start), 1.0f);
    float2* out2 = reinterpret_cast<float2*>(out);
    float2 o = out2[node * 32 + lane];
    o.x = fmaf(ax, inv, o.x);
    o.y = fmaf(ay, inv, o.y);
    out2[node * 32 + lane] = o;
}

// ---------------------------------------------------------------------------
extern "C" void kernel_launch(void* const* d_in, const int* in_sizes, int n_in,
                              void* d_out, int out_size)
{
    const float* x   = (const float*)d_in[0];
    const int*   ei  = (const int*)d_in[1];    // int32 (JAX x64-disabled)
    const float* Wm  = (const float*)d_in[2];
    const float* bm  = (const float*)d_in[3];
    const float* Ws  = (const float*)d_in[4];
    const float* bs  = (const float*)d_in[5];
    float*       out = (float*)d_out;

    (void)in_sizes; (void)n_in; (void)out_size;

    // 1) zero degree counters
    zero_counts_kernel<<<(NN + 255) / 256, 256>>>();

    // 2) dual GEMM (4-node register blocking) + fused degree histogram
    dual_gemm_kernel<<<GEMM_BLOCKS, 256>>>(x, Wm, bm, Ws, bs, ei, out);

    // 3) grid scan -> offsets + cursors
    scan1_kernel<<<SCAN_BLOCKS, 256>>>();
    scan2_kernel<<<1, 32>>>();
    scan3_kernel<<<SCAN_BLOCKS, 256>>>();

    // 4) position scatter -> destination-grouped source list
    pos_kernel<<<(NE + 255) / 256, 256>>>(ei);

    // 5) gather + mean + self-add (atomic-free)
    aggregate_kernel<<<(NN + 7) / 8, 256>>>(out);
}

// round 12
// speedup vs baseline: 2.5705x; 1.0009x over previous
#include <cuda_runtime.h>
#include <cuda_bf16.h>

#define NN 50000
#define NE 800000
#define D  64
#define WPAD 68
#define NBLK 64                  // nodes per GEMM block (4 per thread)
#define GEMM_BLOCKS ((NN + NBLK - 1) / NBLK)   // 782
#define SCAN_BLOCKS 196          // 196*256 = 50176 >= NN; 196 = 28*7

// Scratch (allocations forbidden; __device__ globals are the sanctioned path)
__device__ __align__(16) float g_msgs[NN * D];  // x @ Wm^T + bm
__device__ int g_counts[NN];                    // in-degree; zero-init (.bss) and
                                                // reset by scan1 each run
__device__ int g_offsets[NN + 1];               // CSR row offsets (exclusive scan)
__device__ int g_cursor[NN];                    // fill cursors for position scatter
__device__ int g_srcs[NE];                      // destination-grouped source ids
__device__ int g_bsums[SCAN_BLOCKS];            // per-block sums for grid scan

// ---------------------------------------------------------------------------
// Kernel 1: fused dual GEMM (4-node register blocking) + degree histogram.
//   g_msgs = x @ Wm^T + bm   (feeds the gather)
//   out    = x @ Ws^T + bs   (self projection, straight to d_out)
// At the fp32 FFMA roofline (~24us): 12.8M warp-FFMA / 296 per cyc.
// The degree histogram rides along as a grid-stride loop (REDG, no return).
// g_counts is guaranteed zero here: .bss zero-init on load, and scan1 resets
// every element after reading it (replay-safe).
// ---------------------------------------------------------------------------
__global__ __launch_bounds__(256) void dual_gemm_kernel(
    const float* __restrict__ x,
    const float* __restrict__ Wm, const float* __restrict__ bm,
    const float* __restrict__ Ws, const float* __restrict__ bs,
    const int*   __restrict__ ei,
    float* __restrict__ out)
{
    __shared__ float wm_sh[D * WPAD];
    __shared__ float ws_sh[D * WPAD];
    __shared__ float x_sh[NBLK * WPAD];

    const int t = threadIdx.x;
    const int nbase = blockIdx.x * NBLK;

    // Fused degree histogram: 782*256 = 200192 threads, 4 edges each.
    for (int e = blockIdx.x * 256 + t; e < NE; e += GEMM_BLOCKS * 256) {
        int c = __ldg(&ei[NE + e]);
        c = min(max(c, 0), NN - 1);
        atomicAdd(&g_counts[c], 1);
    }

    // Load both W matrices transposed: Wsh[k][d] = W[d][k]
    for (int i = t; i < D * D; i += 256) {
        int d = i >> 6;
        int k = i & 63;
        wm_sh[k * WPAD + d] = Wm[i];
        ws_sh[k * WPAD + d] = Ws[i];
    }
    // Load x tile (64 nodes x 64) via float4; clamp OOB rows (stores predicated)
    for (int v = t; v < NBLK * 16; v += 256) {
        int row = v >> 4;
        int c4  = (v & 15) * 4;
        int gnode = min(nbase + row, NN - 1);
        float4 xv = *reinterpret_cast<const float4*>(&x[gnode * D + c4]);
        *reinterpret_cast<float4*>(&x_sh[row * WPAD + c4]) = xv;
    }
    __syncthreads();

    const int g  = t >> 4;          // node group 0..15 (4 nodes each)
    const int dq = (t & 15) * 4;    // output dim quad

    float4 am[4], av[4];
#pragma unroll
    for (int j = 0; j < 4; ++j) {
        am[j] = make_float4(0.f, 0.f, 0.f, 0.f);
        av[j] = make_float4(0.f, 0.f, 0.f, 0.f);
    }

#pragma unroll
    for (int k = 0; k < D; ++k) {
        float4 w1 = *reinterpret_cast<const float4*>(&wm_sh[k * WPAD + dq]);
        float4 w2 = *reinterpret_cast<const float4*>(&ws_sh[k * WPAD + dq]);
#pragma unroll
        for (int j = 0; j < 4; ++j) {
            float xv = x_sh[(g * 4 + j) * WPAD + k];
            am[j].x = fmaf(xv, w1.x, am[j].x);
            am[j].y = fmaf(xv, w1.y, am[j].y);
            am[j].z = fmaf(xv, w1.z, am[j].z);
            am[j].w = fmaf(xv, w1.w, am[j].w);
            av[j].x = fmaf(xv, w2.x, av[j].x);
            av[j].y = fmaf(xv, w2.y, av[j].y);
            av[j].z = fmaf(xv, w2.z, av[j].z);
            av[j].w = fmaf(xv, w2.w, av[j].w);
        }
    }

    float4 bmv = *reinterpret_cast<const float4*>(&bm[dq]);
    float4 bsv = *reinterpret_cast<const float4*>(&bs[dq]);
#pragma unroll
    for (int j = 0; j < 4; ++j) {
        int node = nbase + g * 4 + j;
        if (node < NN) {
            float4 a = am[j], v = av[j];
            a.x += bmv.x; a.y += bmv.y; a.z += bmv.z; a.w += bmv.w;
            v.x += bsv.x; v.y += bsv.y; v.z += bsv.z; v.w += bsv.w;
            const int o = node * D + dq;
            *reinterpret_cast<float4*>(&g_msgs[o]) = a;
            *reinterpret_cast<float4*>(&out[o])    = v;
        }
    }
}

// ---------------------------------------------------------------------------
// Grid scan (3 kernels).
// ---------------------------------------------------------------------------
__device__ __forceinline__ int warp_incl_scan(int v, int lane) {
#pragma unroll
    for (int off = 1; off < 32; off <<= 1) {
        int n = __shfl_up_sync(0xFFFFFFFFu, v, off);
        if (lane >= off) v += n;
    }
    return v;
}

// scan1: per-block exclusive scan of counts + RESET counts to zero for the
// next replay (removes the separate zero_counts launch).
__global__ __launch_bounds__(256) void scan1_kernel() {
    __shared__ int wsum[8];
    const int t = threadIdx.x;
    const int lane = t & 31;
    const int w = t >> 5;
    const int idx = blockIdx.x * 256 + t;

    int v = 0;
    if (idx < NN) {
        v = g_counts[idx];
        g_counts[idx] = 0;          // reset for next graph replay
    }
    int inc = warp_incl_scan(v, lane);
    if (lane == 31) wsum[w] = inc;
    __syncthreads();

    if (w == 0) {
        int s = (lane < 8) ? wsum[lane] : 0;
        int si = warp_incl_scan(s, lane);
        if (lane < 8) wsum[lane] = si - s;   // exclusive warp offsets
        if (lane == 7) g_bsums[blockIdx.x] = si;
    }
    __syncthreads();

    if (idx < NN) g_offsets[idx] = inc - v + wsum[w];   // block-local exclusive
}

// scan2: one warp scans the 196 block sums. All loads issued upfront
// (independent -> one L2 round trip) -> scan entirely in registers.
// 196 = 28 lanes * 7 items.
__global__ void scan2_kernel() {
    const int lane = threadIdx.x;   // 32 threads
    const int base = lane * 7;
    const bool act = (lane < 28);

    int v[7];
#pragma unroll
    for (int i = 0; i < 7; ++i) v[i] = act ? g_bsums[base + i] : 0;

    int s = 0;
#pragma unroll
    for (int i = 0; i < 7; ++i) s += v[i];

    int run = warp_incl_scan(s, lane) - s;   // exclusive prefix of this lane
#pragma unroll
    for (int i = 0; i < 7; ++i) {
        if (act) g_bsums[base + i] = run;
        run += v[i];
    }
    if (lane == 0) g_offsets[NN] = NE;   // every (clamped) edge is counted
}

// scan3: add block offsets, materialize offsets + fill cursors.
__global__ __launch_bounds__(256) void scan3_kernel() {
    const int idx = blockIdx.x * 256 + threadIdx.x;
    if (idx < NN) {
        int o = g_offsets[idx] + g_bsums[blockIdx.x];
        g_offsets[idx] = o;
        g_cursor[idx]  = o;
    }
}

// ---------------------------------------------------------------------------
// Position scatter: each edge claims a slot in its destination's CSR segment
// and records its SOURCE id there. 800k returning int atomics.
// ---------------------------------------------------------------------------
__global__ __launch_bounds__(256) void pos_kernel(const int* __restrict__ ei) {
    int e = blockIdx.x * 256 + threadIdx.x;
    if (e < NE) {
        int r = __ldg(&ei[e]);
        int c = __ldg(&ei[NE + e]);
        r = min(max(r, 0), NN - 1);
        c = min(max(c, 0), NN - 1);
        int p = atomicAdd(&g_cursor[c], 1);
        g_srcs[p] = r;
    }
}

// ---------------------------------------------------------------------------
// Warp-per-node gather + mean + self-add. ZERO atomics.
// Lane l owns dims {2l, 2l+1} via float2 (LDG.64). 4x edge unroll keeps 4
// independent 64-bit loads in flight (avg degree 16). At the L2-read
// roofline (~205MB / 6300 B/cyc).
// ---------------------------------------------------------------------------
__global__ __launch_bounds__(256) void aggregate_kernel(float* __restrict__ out) {
    const int node = blockIdx.x * 8 + (threadIdx.x >> 5);
    if (node >= NN) return;
    const int lane = threadIdx.x & 31;

    const int start = __ldg(&g_offsets[node]);
    const int end   = __ldg(&g_offsets[node + 1]);

    const float2* __restrict__ msgs2 = reinterpret_cast<const float2*>(g_msgs);

    float ax = 0.f, ay = 0.f;
    int j = start;
    for (; j + 4 <= end; j += 4) {
        int s0 = __ldg(&g_srcs[j]);
        int s1 = __ldg(&g_srcs[j + 1]);
        int s2 = __ldg(&g_srcs[j + 2]);
        int s3 = __ldg(&g_srcs[j + 3]);
        float2 v0 = __ldg(&msgs2[s0 * 32 + lane]);
        float2 v1 = __ldg(&msgs2[s1 * 32 + lane]);
        float2 v2 = __ldg(&msgs2[s2 * 32 + lane]);
        float2 v3 = __ldg(&msgs2[s3 * 32 + lane]);
        ax += (v0.x + v1.x) + (v2.x + v3.x);
        ay += (v0.y + v1.y) + (v2.y + v3.y);
    }
    for (; j < end; ++j) {
        int s0 = __ldg(&g_srcs[j]);
        float2 v0 = __ldg(&msgs2[s0 * 32 + lane]);
        ax += v0.x;
        ay += v0.y;
    }

    const float inv = 1.0f / fmaxf((float)(end - start), 1.0f);
    float2* out2 = reinterpret_cast<float2*>(out);
    float2 o = out2[node * 32 + lane];
    o.x = fmaf(ax, inv, o.x);
    o.y = fmaf(ay, inv, o.y);
    out2[node * 32 + lane] = o;
}

// ---------------------------------------------------------------------------
extern "C" void kernel_launch(void* const* d_in, const int* in_sizes, int n_in,
                              void* d_out, int out_size)
{
    const float* x   = (const float*)d_in[0];
    const int*   ei  = (const int*)d_in[1];    // int32 (JAX x64-disabled)
    const float* Wm  = (const float*)d_in[2];
    const float* bm  = (const float*)d_in[3];
    const float* Ws  = (const float*)d_in[4];
    const float* bs  = (const float*)d_in[5];
    float*       out = (float*)d_out;

    (void)in_sizes; (void)n_in; (void)out_size;

    // 1) dual GEMM (4-node register blocking) + fused degree histogram
    //    (g_counts is zero: .bss init on first run, reset by scan1 thereafter)
    dual_gemm_kernel<<<GEMM_BLOCKS, 256>>>(x, Wm, bm, Ws, bs, ei, out);

    // 2) grid scan -> offsets + cursors (scan1 also resets g_counts)
    scan1_kernel<<<SCAN_BLOCKS, 256>>>();
    scan2_kernel<<<1, 32>>>();
    scan3_kernel<<<SCAN_BLOCKS, 256>>>();

    // 3) position scatter -> destination-grouped source list
    pos_kernel<<<(NE + 255) / 256, 256>>>(ei);

    // 4) gather + mean + self-add (atomic-free)
    aggregate_kernel<<<(NN + 7) / 8, 256>>>(out);
}